// round 15
// baseline (speedup 1.0000x reference)
#include <cuda_runtime.h>
#include <cuda_bf16.h>
#include <math.h>
#include <stdint.h>

#define TT 1024
#define HH 512

// ---- persistent state (device globals; no allocation allowed) ----
__device__ float g_h[2][32][2][512];   // [parity][group][batch-in-group][k]
__device__ int   g_bar[32];            // per-group arrival counters
__device__ __nv_bfloat16 g_xhi[64u * 1024u * 512u];
__device__ __nv_bfloat16 g_xlo[64u * 1024u * 512u];
__device__ __nv_bfloat16 g_whi[512 * 512];
__device__ __nv_bfloat16 g_wlo[512 * 512];

// ---------------- packed f32x2 helpers ----------------
__device__ __forceinline__ unsigned long long pack2(float x, float y) {
    unsigned long long r;
    asm("mov.b64 %0, {%1, %2};" : "=l"(r) : "f"(x), "f"(y));
    return r;
}
__device__ __forceinline__ unsigned long long fma2(unsigned long long a,
                                                   unsigned long long b,
                                                   unsigned long long c) {
    unsigned long long d;
    asm("fma.rn.f32x2 %0, %1, %2, %3;" : "=l"(d) : "l"(a), "l"(b), "l"(c));
    return d;
}
__device__ __forceinline__ float2 unpack2(unsigned long long v) {
    float2 r;
    asm("mov.b64 {%0, %1}, %2;" : "=f"(r.x), "=f"(r.y) : "l"(v));
    return r;
}

// ---------------- tensor helpers ----------------
__device__ __forceinline__ uint32_t smem_u32(const void* p) {
    uint32_t a;
    asm("{ .reg .u64 t; cvta.to.shared.u64 t, %1; cvt.u32.u64 %0, t; }"
        : "=r"(a) : "l"(p));
    return a;
}
__device__ __forceinline__ uint32_t sw128(uint32_t byte_off) {
    return byte_off ^ ((byte_off >> 3) & 0x70);
}
__device__ __forceinline__ void ldsm_x4(uint32_t& r0, uint32_t& r1,
                                        uint32_t& r2, uint32_t& r3, uint32_t addr) {
    asm volatile("ldmatrix.sync.aligned.m8n8.x4.shared.b16 {%0,%1,%2,%3}, [%4];"
                 : "=r"(r0), "=r"(r1), "=r"(r2), "=r"(r3) : "r"(addr));
}
__device__ __forceinline__ void ldsm_x4t(uint32_t& r0, uint32_t& r1,
                                         uint32_t& r2, uint32_t& r3, uint32_t addr) {
    asm volatile("ldmatrix.sync.aligned.m8n8.x4.trans.shared.b16 {%0,%1,%2,%3}, [%4];"
                 : "=r"(r0), "=r"(r1), "=r"(r2), "=r"(r3) : "r"(addr));
}
__device__ __forceinline__ void mma_bf16(float* d, const uint32_t* a, const uint32_t* b) {
    asm volatile("mma.sync.aligned.m16n8k16.row.col.f32.bf16.bf16.f32 "
                 "{%0,%1,%2,%3}, {%4,%5,%6,%7}, {%8,%9}, {%0,%1,%2,%3};"
                 : "+f"(d[0]), "+f"(d[1]), "+f"(d[2]), "+f"(d[3])
                 : "r"(a[0]), "r"(a[1]), "r"(a[2]), "r"(a[3]), "r"(b[0]), "r"(b[1]));
}
__device__ __forceinline__ void cpasync16(uint32_t sdst, const void* gsrc) {
    asm volatile("cp.async.cg.shared.global [%0], [%1], 16;" :: "r"(sdst), "l"(gsrc));
}

// ===================== conversion: fp32 -> bf16 hi/lo split ========================
__global__ void __launch_bounds__(256) convert_x_kernel(const float* __restrict__ x) {
    const int N4 = 64 * 1024 * 512 / 4;
    for (int i = blockIdx.x * blockDim.x + threadIdx.x; i < N4;
         i += gridDim.x * blockDim.x) {
        float4 v = ((const float4*)x)[i];
        __nv_bfloat16 h0 = __float2bfloat16(v.x);
        __nv_bfloat16 h1 = __float2bfloat16(v.y);
        __nv_bfloat16 h2 = __float2bfloat16(v.z);
        __nv_bfloat16 h3 = __float2bfloat16(v.w);
        __nv_bfloat16 l0 = __float2bfloat16(v.x - __bfloat162float(h0));
        __nv_bfloat16 l1 = __float2bfloat16(v.y - __bfloat162float(h1));
        __nv_bfloat16 l2 = __float2bfloat16(v.z - __bfloat162float(h2));
        __nv_bfloat16 l3 = __float2bfloat16(v.w - __bfloat162float(h3));
        __nv_bfloat162* dh = (__nv_bfloat162*)(g_xhi + 4 * (size_t)i);
        __nv_bfloat162* dl = (__nv_bfloat162*)(g_xlo + 4 * (size_t)i);
        dh[0] = __halves2bfloat162(h0, h1); dh[1] = __halves2bfloat162(h2, h3);
        dl[0] = __halves2bfloat162(l0, l1); dl[1] = __halves2bfloat162(l2, l3);
    }
}
__global__ void __launch_bounds__(256) convert_w_kernel(const float* __restrict__ Wg) {
    if (blockIdx.x == 0 && threadIdx.x < 32) g_bar[threadIdx.x] = 0;  // phase-2 reset
    const int N4 = 512 * 512 / 4;
    for (int i = blockIdx.x * blockDim.x + threadIdx.x; i < N4;
         i += gridDim.x * blockDim.x) {
        float4 v = ((const float4*)Wg)[i];
        __nv_bfloat16 h0 = __float2bfloat16(v.x);
        __nv_bfloat16 h1 = __float2bfloat16(v.y);
        __nv_bfloat16 h2 = __float2bfloat16(v.z);
        __nv_bfloat16 h3 = __float2bfloat16(v.w);
        __nv_bfloat16 l0 = __float2bfloat16(v.x - __bfloat162float(h0));
        __nv_bfloat16 l1 = __float2bfloat16(v.y - __bfloat162float(h1));
        __nv_bfloat16 l2 = __float2bfloat16(v.z - __bfloat162float(h2));
        __nv_bfloat16 l3 = __float2bfloat16(v.w - __bfloat162float(h3));
        __nv_bfloat162* dh = (__nv_bfloat162*)(g_whi + 4 * (size_t)i);
        __nv_bfloat162* dl = (__nv_bfloat162*)(g_wlo + 4 * (size_t)i);
        dh[0] = __halves2bfloat162(h0, h1); dh[1] = __halves2bfloat162(h2, h3);
        dl[0] = __halves2bfloat162(l0, l1); dl[1] = __halves2bfloat162(l2, l3);
    }
}

// ===================== Phase 1: tensor GEMM  out = x@Wx + b (unchanged R10) ========
#define AHI_B 0
#define ALO_B 16384
#define BH0_B 32768
#define BH1_B 40960
#define BL0_B 49152
#define BL1_B 57344
#define STAGE_B 65536

__global__ void __launch_bounds__(256) gemm_bf16_kernel(
    const float* __restrict__ bias, float* __restrict__ C)
{
    extern __shared__ __align__(1024) char smem[];
    const uint32_t sb = smem_u32(smem);

    const int tid = threadIdx.x;
    const int l   = tid & 31;
    const int wid = tid >> 5;
    const int wm  = wid & 1;
    const int wn  = wid >> 1;
    const int half = wn >> 1;
    const int nh   = (wn & 1) * 32;
    const int m0  = blockIdx.x * 128;
    const int n0  = blockIdx.y * 128;

    float acc[4][4][4];
#pragma unroll
    for (int i = 0; i < 4; i++)
#pragma unroll
        for (int j = 0; j < 4; j++)
#pragma unroll
            for (int q = 0; q < 4; q++) acc[i][j][q] = 0.0f;

    auto load_tile = [&](int kt, int stg) {
        const uint32_t s0 = sb + stg * STAGE_B;
        const int k0 = kt * 64;
#pragma unroll
        for (int j = 0; j < 4; j++) {
            int cch = tid + j * 256;
            int row = cch >> 3, cc = cch & 7;
            size_t gm = (size_t)(m0 + row) * 512 + k0 + cc * 8;
            uint32_t so = sw128(row * 128 + cc * 16);
            cpasync16(s0 + AHI_B + so, g_xhi + gm);
            cpasync16(s0 + ALO_B + so, g_xlo + gm);
        }
#pragma unroll
        for (int j = 0; j < 2; j++) {
            int cch = tid + j * 256;
            int row = cch >> 3, cc = cch & 7;
            size_t gm0 = (size_t)(k0 + row) * 512 + n0 + cc * 8;
            uint32_t so = sw128(row * 128 + cc * 16);
            cpasync16(s0 + BH0_B + so, g_whi + gm0);
            cpasync16(s0 + BH1_B + so, g_whi + gm0 + 64);
            cpasync16(s0 + BL0_B + so, g_wlo + gm0);
            cpasync16(s0 + BL1_B + so, g_wlo + gm0 + 64);
        }
    };

    load_tile(0, 0);
    asm volatile("cp.async.commit_group;");

    for (int kt = 0; kt < 8; kt++) {
        if (kt < 7) {
            load_tile(kt + 1, (kt + 1) & 1);
            asm volatile("cp.async.commit_group;");
            asm volatile("cp.async.wait_group 1;");
        } else {
            asm volatile("cp.async.wait_group 0;");
        }
        __syncthreads();

        const uint32_t s0 = sb + (kt & 1) * STAGE_B;
        const uint32_t bbase = s0 + (half ? BH1_B : BH0_B);
        const uint32_t blbase = s0 + (half ? BL1_B : BL0_B);

#pragma unroll
        for (int kk = 0; kk < 4; kk++) {
            uint32_t ahi[4][4], alo[4][4], bhi[4][2], blo[4][2];
#pragma unroll
            for (int mb = 0; mb < 4; mb++) {
                uint32_t ao = sw128((wm * 64 + mb * 16 + (l & 15)) * 128 +
                                    (kk * 16 + ((l >> 4) << 3)) * 2);
                ldsm_x4(ahi[mb][0], ahi[mb][1], ahi[mb][2], ahi[mb][3], s0 + AHI_B + ao);
                ldsm_x4(alo[mb][0], alo[mb][1], alo[mb][2], alo[mb][3], s0 + ALO_B + ao);
            }
#pragma unroll
            for (int nb2 = 0; nb2 < 2; nb2++) {
                uint32_t krow = kk * 16 + (l & 7) + (((l >> 3) & 1) << 3);
                uint32_t ncol = nh + (nb2 << 4) + ((l >> 4) << 3);
                uint32_t bo = sw128(krow * 128 + ncol * 2);
                uint32_t r0, r1, r2, r3;
                ldsm_x4t(r0, r1, r2, r3, bbase + bo);
                bhi[2 * nb2][0] = r0; bhi[2 * nb2][1] = r1;
                bhi[2 * nb2 + 1][0] = r2; bhi[2 * nb2 + 1][1] = r3;
                ldsm_x4t(r0, r1, r2, r3, blbase + bo);
                blo[2 * nb2][0] = r0; blo[2 * nb2][1] = r1;
                blo[2 * nb2 + 1][0] = r2; blo[2 * nb2 + 1][1] = r3;
            }
#pragma unroll
            for (int mb = 0; mb < 4; mb++)
#pragma unroll
                for (int nb = 0; nb < 4; nb++) {
                    mma_bf16(acc[mb][nb], ahi[mb], bhi[nb]);
                    mma_bf16(acc[mb][nb], ahi[mb], blo[nb]);
                    mma_bf16(acc[mb][nb], alo[mb], bhi[nb]);
                }
        }
        __syncthreads();
    }

    const int r  = l >> 2;
    const int cq = (l & 3) * 2;
#pragma unroll
    for (int mb = 0; mb < 4; mb++) {
#pragma unroll
        for (int nb = 0; nb < 4; nb++) {
            int colg = n0 + wn * 32 + nb * 8 + cq;
            float2 bv = *(const float2*)(bias + colg);
            int row0 = m0 + wm * 64 + mb * 16 + r;
            float2 o0 = make_float2(acc[mb][nb][0] + bv.x, acc[mb][nb][1] + bv.y);
            float2 o1 = make_float2(acc[mb][nb][2] + bv.x, acc[mb][nb][3] + bv.y);
            *(float2*)(C + (size_t)row0 * 512 + colg) = o0;
            *(float2*)(C + (size_t)(row0 + 8) * 512 + colg) = o1;
        }
    }
}

// ===================== Phase 2: dual-chain pipelined recurrence ====================
// 128 CTAs. CTA (gp, c). Chain A = group 2gp (batches 4gp..4gp+1), chain B = group
// 2gp+1 (batches 4gp+2..4gp+3), both sharing the same Wh register slice. While one
// chain's release->counter->acquire RTT is in flight, the CTA computes the other.
// Hardened poll: relaxed probe + nanosleep backoff, acquire only to confirm.
__device__ __forceinline__ void poll_bar(int* ctr, int target) {
    int v;
    asm volatile("ld.relaxed.gpu.global.s32 %0, [%1];" : "=r"(v) : "l"(ctr) : "memory");
    unsigned ns = 32;
    while (v < target) {
        __nanosleep(ns);
        if (ns < 256) ns <<= 1;
        asm volatile("ld.relaxed.gpu.global.s32 %0, [%1];" : "=r"(v) : "l"(ctr) : "memory");
    }
    asm volatile("ld.acquire.gpu.global.s32 %0, [%1];" : "=r"(v) : "l"(ctr) : "memory");
}
__device__ __forceinline__ void release_bar(int* ctr) {
    asm volatile("red.release.gpu.global.add.s32 [%0], 1;" :: "l"(ctr) : "memory");
}

__global__ void __launch_bounds__(256, 1) recurrent_kernel(
    const float* __restrict__ Wg, float* __restrict__ out)
{
    __shared__ __align__(16) float4 hsA[2][256];  // [batch][k/2] duplicated pairs
    __shared__ __align__(16) float4 hsB[2][256];
    __shared__ float red[8][132];

    const int tid = threadIdx.x;
    const int gp  = blockIdx.x >> 3;   // 0..15
    const int c   = blockIdx.x & 7;    // col-slice 0..7
    const int kc  = tid >> 5;          // warp id == K-chunk 0..7
    const int jg  = tid & 31;          // cols 2jg, 2jg+1 within slice
    const int grpA = 2 * gp, grpB = 2 * gp + 1;

    // ---- Wh slice into registers: w[k] = {Wh[kc*64+k][c*64+2jg], [..+2jg+1]} ----
    unsigned long long w[64];
#pragma unroll
    for (int k = 0; k < 64; k++) {
        const float* p = Wg + (size_t)(512 + kc * 64 + k) * 512 + c * 64 + jg * 2;
        w[k] = *(const unsigned long long*)p;
    }
    for (int i = tid; i < 512; i += 256) {
        ((float4*)hsA)[i] = make_float4(0.f, 0.f, 0.f, 0.f);
        ((float4*)hsB)[i] = make_float4(0.f, 0.f, 0.f, 0.f);
    }
    __syncthreads();

    const int boE  = (tid >> 6) & 1;
    const int colE = tid & 63;
    float* outA = out + (size_t)(4 * gp + boE) * TT * HH + c * 64 + colE;
    float* outB = out + (size_t)(4 * gp + 2 + boE) * TT * HH + c * 64 + colE;
    int* ctrA = &g_bar[grpA];
    int* ctrB = &g_bar[grpB];
    const int rb = tid >> 7;            // batch-in-group 0..1
    const int rq = (tid & 127) * 2;     // dest float4 index (duplicated)

#pragma unroll 1
    for (int t = 0; t < TT; t++) {
        const bool more = (t + 1 < TT);

        // ================= chain A: compute =================
        float xwA = (tid < 128) ? outA[(size_t)t * HH] : 0.0f;
        {
            const ulonglong2* h0 = (const ulonglong2*)&hsA[0][kc * 32];
            const ulonglong2* h1 = (const ulonglong2*)&hsA[1][kc * 32];
            unsigned long long ae0 = 0, ao0 = 0, ae1 = 0, ao1 = 0;
#pragma unroll
            for (int k2 = 0; k2 < 32; k2++) {
                ulonglong2 q0 = h0[k2];
                ulonglong2 q1 = h1[k2];
                unsigned long long we = w[2 * k2], wo = w[2 * k2 + 1];
                ae0 = fma2(q0.x, we, ae0);
                ao0 = fma2(q0.y, wo, ao0);
                ae1 = fma2(q1.x, we, ae1);
                ao1 = fma2(q1.y, wo, ao1);
            }
            float2 e0 = unpack2(ae0), o0 = unpack2(ao0);
            float2 e1 = unpack2(ae1), o1 = unpack2(ao1);
            *(float2*)&red[kc][0 * 64 + jg * 2] = make_float2(e0.x + o0.x, e0.y + o0.y);
            *(float2*)&red[kc][1 * 64 + jg * 2] = make_float2(e1.x + o1.x, e1.y + o1.y);
        }
        __syncthreads();

        // ---- chain B prep (poll + reload) overlapped with A epilogue ----
        float4 rB;
        if (t > 0) {
            poll_bar(ctrB, 8 * t);
            rB = __ldcg((const float4*)&g_h[t & 1][grpB][0][0] + tid);
        }
        if (tid < 128) {
            float z = xwA;
#pragma unroll
            for (int q = 0; q < 8; q++) z += red[q][tid];
            float hv = tanhf(z);
            outA[(size_t)t * HH] = hv;
            if (more) __stcg(&g_h[(t + 1) & 1][grpA][boE][c * 64 + colE], hv);
        }
        if (t > 0) {
            hsB[rb][rq + 0] = make_float4(rB.x, rB.x, rB.y, rB.y);
            hsB[rb][rq + 1] = make_float4(rB.z, rB.z, rB.w, rB.w);
        }
        __syncthreads();
        if (tid == 0 && more) release_bar(ctrA);

        // ================= chain B: compute =================
        float xwB = (tid < 128) ? outB[(size_t)t * HH] : 0.0f;
        {
            const ulonglong2* h0 = (const ulonglong2*)&hsB[0][kc * 32];
            const ulonglong2* h1 = (const ulonglong2*)&hsB[1][kc * 32];
            unsigned long long ae0 = 0, ao0 = 0, ae1 = 0, ao1 = 0;
#pragma unroll
            for (int k2 = 0; k2 < 32; k2++) {
                ulonglong2 q0 = h0[k2];
                ulonglong2 q1 = h1[k2];
                unsigned long long we = w[2 * k2], wo = w[2 * k2 + 1];
                ae0 = fma2(q0.x, we, ae0);
                ao0 = fma2(q0.y, wo, ao0);
                ae1 = fma2(q1.x, we, ae1);
                ao1 = fma2(q1.y, wo, ao1);
            }
            float2 e0 = unpack2(ae0), o0 = unpack2(ao0);
            float2 e1 = unpack2(ae1), o1 = unpack2(ao1);
            *(float2*)&red[kc][0 * 64 + jg * 2] = make_float2(e0.x + o0.x, e0.y + o0.y);
            *(float2*)&red[kc][1 * 64 + jg * 2] = make_float2(e1.x + o1.x, e1.y + o1.y);
        }
        __syncthreads();

        // ---- chain A prep for t+1 (poll + reload) overlapped with B epilogue ----
        float4 rA;
        if (more) {
            poll_bar(ctrA, 8 * (t + 1));
            rA = __ldcg((const float4*)&g_h[(t + 1) & 1][grpA][0][0] + tid);
        }
        if (tid < 128) {
            float z = xwB;
#pragma unroll
            for (int q = 0; q < 8; q++) z += red[q][tid];
            float hv = tanhf(z);
            outB[(size_t)t * HH] = hv;
            if (more) __stcg(&g_h[(t + 1) & 1][grpB][boE][c * 64 + colE], hv);
        }
        if (more) {
            hsA[rb][rq + 0] = make_float4(rA.x, rA.x, rA.y, rA.y);
            hsA[rb][rq + 1] = make_float4(rA.z, rA.z, rA.w, rA.w);
        }
        __syncthreads();
        if (tid == 0 && more) release_bar(ctrB);
    }
}

// ======================================================================================
extern "C" void kernel_launch(void* const* d_in, const int* in_sizes, int n_in,
                              void* d_out, int out_size) {
    (void)in_sizes; (void)n_in; (void)out_size;
    const float* x  = (const float*)d_in[0];   // [64,1024,512]
    const float* Wg = (const float*)d_in[1];   // [1024,512]
    const float* bb = (const float*)d_in[2];   // [512]
    float* out = (float*)d_out;                // [64,1024,512]

    static int smem_set = 0;
    if (!smem_set) {
        cudaFuncSetAttribute(gemm_bf16_kernel,
                             cudaFuncAttributeMaxDynamicSharedMemorySize, 2 * STAGE_B);
        smem_set = 1;
    }

    convert_x_kernel<<<2048, 256>>>(x);
    convert_w_kernel<<<64, 256>>>(Wg);
    gemm_bf16_kernel<<<dim3(512, 4), 256, 2 * STAGE_B>>>(bb, out);
    recurrent_kernel<<<128, 256>>>(Wg, out);
}